// round 2
// baseline (speedup 1.0000x reference)
#include <cuda_runtime.h>
#include <math.h>

#define NE 40000
#define NRL 500
#define ED 200000
#define E2 50000
#define ET 250000

static constexpr size_t SZ_MAT = (size_t)NE * 256;
static constexpr size_t O_PA  = 0;
static constexpr size_t O_PB  = O_PA  + SZ_MAT;
static constexpr size_t O_ENT = O_PB  + SZ_MAT;
static constexpr size_t O_X   = O_ENT + SZ_MAT;
static constexpr size_t O_QA  = O_X   + SZ_MAT;
static constexpr size_t O_QB  = O_QA  + SZ_MAT;
static constexpr size_t O_AGG = O_QB  + SZ_MAT;
static constexpr size_t O_PC  = O_AGG + SZ_MAT;
static constexpr size_t O_QC  = O_PC  + (size_t)NRL * 256;
static constexpr size_t O_WA  = O_QC  + (size_t)NRL * 256;
static constexpr size_t O_WB  = O_WA  + 128 * 256;
static constexpr size_t O_WC  = O_WB  + 128 * 256;
static constexpr size_t O_LOG = O_WC  + 128 * 256;
static constexpr size_t O_MAX = O_LOG + (size_t)ET * 4;
static constexpr size_t O_SUM = O_MAX + (size_t)NE * 4;
static constexpr size_t O_CS  = O_SUM + (size_t)NE * 4;
static constexpr size_t O_CQ  = O_CS  + 256;
static constexpr size_t O_MU  = O_CQ  + 256;
static constexpr size_t O_RS  = O_MU  + 256;
static constexpr size_t O_END = O_RS  + 256;

__device__ float g_S[O_END];

// ---------- helpers ----------
__device__ __forceinline__ unsigned fenc(float f) {
    unsigned u = __float_as_uint(f);
    return (u & 0x80000000u) ? ~u : (u | 0x80000000u);
}
__device__ __forceinline__ float fdec(unsigned u) {
    return (u & 0x80000000u) ? __uint_as_float(u & 0x7FFFFFFFu)
                             : __uint_as_float(~u);
}
__device__ __forceinline__ void edge_rc(int e, const int* __restrict__ ei,
                                        const int* __restrict__ et,
                                        const int* __restrict__ i2,
                                        int& row, int& col, int& rt, int& rt2) {
    if (e < ED) {
        row = ei[ED + e];
        col = ei[e];
        rt  = et[e];
        rt2 = -1;
    } else {
        const int* p = i2 + 4 * (e - ED);
        row = p[3]; col = p[0]; rt = p[1]; rt2 = p[2];
    }
}
__device__ __forceinline__ int edge_row(int e, const int* __restrict__ ei,
                                        const int* __restrict__ i2) {
    return (e < ED) ? ei[ED + e] : i2[4 * (e - ED) + 3];
}
__device__ __forceinline__ float4 f4add(float4 a, float4 b) {
    return make_float4(a.x + b.x, a.y + b.y, a.z + b.z, a.w + b.w);
}
__device__ __forceinline__ float dot4(float4 a, float4 b) {
    return a.x * b.x + a.y * b.y + a.z * b.z + a.w * b.w;
}

// ---------- weight repack: W_heads (4,384,64) -> WA/WB/WC (128,256) head-major cols ----------
__global__ void k_prep_w(const float* __restrict__ Wh) {
    int t = blockIdx.x * blockDim.x + threadIdx.x;
    if (t >= 128 * 256) return;
    int k = t >> 8, c = t & 255;
    int h = c >> 6, j = c & 63;
    g_S[O_WA + t] = Wh[((h * 384) + k) * 64 + j];
    g_S[O_WB + t] = Wh[((h * 384) + 128 + k) * 64 + j];
    g_S[O_WC + t] = Wh[((h * 384) + 256 + k) * 64 + j];
}

// ---------- zero scratch for a softmax+agg round ----------
__global__ void k_init() {
    size_t i = (size_t)blockIdx.x * blockDim.x + threadIdx.x;
    if (i < SZ_MAT) g_S[O_AGG + i] = 0.f;
    if (i < (size_t)NE * 4) { g_S[O_MAX + i] = 0.f; g_S[O_SUM + i] = 0.f; }
    if (i < 256) { g_S[O_CS + i] = 0.f; g_S[O_CQ + i] = 0.f; }
}

// ---------- simple fp32 tiled GEMM: C[M,N] = A[M,K] @ B[K,N] ----------
#define BM 128
#define BN 64
#define BK 16
__global__ __launch_bounds__(256) void k_gemm(const float* __restrict__ A,
                                              const float* __restrict__ B,
                                              float* __restrict__ C,
                                              int M, int N, int K) {
    __shared__ float As[BK][BM + 4];
    __shared__ float Bs[BK][BN];
    const int bm = blockIdx.y * BM;
    const int bn = blockIdx.x * BN;
    const int tid = threadIdx.x;
    const int tx = tid & 15;
    const int ty = tid >> 4;
    float acc[8][4];
#pragma unroll
    for (int i = 0; i < 8; i++)
#pragma unroll
        for (int j = 0; j < 4; j++) acc[i][j] = 0.f;

    for (int k0 = 0; k0 < K; k0 += BK) {
#pragma unroll
        for (int l = 0; l < 2; l++) {
            int idx = tid + l * 256;
            int ar = idx >> 2;
            int ac = (idx & 3) << 2;
            float4 v = make_float4(0.f, 0.f, 0.f, 0.f);
            if (bm + ar < M)
                v = *(const float4*)(A + (size_t)(bm + ar) * K + k0 + ac);
            As[ac + 0][ar] = v.x; As[ac + 1][ar] = v.y;
            As[ac + 2][ar] = v.z; As[ac + 3][ar] = v.w;
        }
        {
            int br = tid >> 4;
            int bc = (tid & 15) << 2;
            *(float4*)&Bs[br][bc] =
                *(const float4*)(B + (size_t)(k0 + br) * N + bn + bc);
        }
        __syncthreads();
#pragma unroll
        for (int k = 0; k < BK; k++) {
            float4 a0 = *(const float4*)&As[k][ty * 8];
            float4 a1 = *(const float4*)&As[k][ty * 8 + 4];
            float4 b0 = *(const float4*)&Bs[k][tx * 4];
            float ar_[8] = {a0.x, a0.y, a0.z, a0.w, a1.x, a1.y, a1.z, a1.w};
            float br_[4] = {b0.x, b0.y, b0.z, b0.w};
#pragma unroll
            for (int i = 0; i < 8; i++)
#pragma unroll
                for (int j = 0; j < 4; j++)
                    acc[i][j] = fmaf(ar_[i], br_[j], acc[i][j]);
        }
        __syncthreads();
    }
#pragma unroll
    for (int i = 0; i < 8; i++) {
        int r = bm + ty * 8 + i;
        if (r < M) {
            float4 o = make_float4(acc[i][0], acc[i][1], acc[i][2], acc[i][3]);
            *(float4*)(C + (size_t)r * N + bn + (tx << 2)) = o;
        }
    }
}

// ---------- L1 pass1: logits (4 heads) + per-node per-head atomic max ----------
__global__ void k_l1p1(const int* __restrict__ ei, const int* __restrict__ et,
                       const int* __restrict__ i2, const float* __restrict__ ah) {
    int gt = blockIdx.x * blockDim.x + threadIdx.x;
    int e = gt >> 5, lane = gt & 31;
    if (e >= ET) return;
    int row, col, rt, rt2;
    edge_rc(e, ei, et, i2, row, col, rt, rt2);
    int li = lane * 4;
    const float* PA = g_S + O_PA + (size_t)row * 256;
    const float* PB = g_S + O_PB + (size_t)col * 256;
    const float* PC = g_S + O_PC;
    float4 e0 = f4add(*(const float4*)(PA + li), *(const float4*)(PB + li));
    float4 e1 = f4add(*(const float4*)(PA + 128 + li), *(const float4*)(PB + 128 + li));
    e0 = f4add(e0, *(const float4*)(PC + (size_t)rt * 256 + li));
    e1 = f4add(e1, *(const float4*)(PC + (size_t)rt * 256 + 128 + li));
    if (rt2 >= 0) {
        e0 = f4add(e0, *(const float4*)(PC + (size_t)rt2 * 256 + li));
        e1 = f4add(e1, *(const float4*)(PC + (size_t)rt2 * 256 + 128 + li));
    }
    int ha = lane >> 4;  // head of e0 (0/1); head of e1 is 2+ha
    float4 av0 = *(const float4*)(ah + ha * 64 + (li & 63));
    float4 av1 = *(const float4*)(ah + (2 + ha) * 64 + (li & 63));
    float p0 = dot4(e0, av0);
    float p1 = dot4(e1, av1);
#pragma unroll
    for (int o = 8; o >= 1; o >>= 1) {
        p0 += __shfl_xor_sync(0xffffffffu, p0, o);
        p1 += __shfl_xor_sync(0xffffffffu, p1, o);
    }
    if ((lane & 15) == 0) {
        float l0 = p0 > 0.f ? p0 : 0.2f * p0;
        float l1 = p1 > 0.f ? p1 : 0.2f * p1;
        g_S[O_LOG + (size_t)e * 4 + ha] = l0;
        g_S[O_LOG + (size_t)e * 4 + 2 + ha] = l1;
        unsigned* mx = (unsigned*)(g_S + O_MAX);
        atomicMax(&mx[row * 4 + ha], fenc(l0));
        atomicMax(&mx[row * 4 + 2 + ha], fenc(l1));
    }
}

// ---------- L1 pass2: exp + atomic sum ----------
__global__ void k_l1p2(const int* __restrict__ ei, const int* __restrict__ et,
                       const int* __restrict__ i2) {
    int t = blockIdx.x * blockDim.x + threadIdx.x;
    if (t >= ET * 4) return;
    int e = t >> 2, h = t & 3;
    int row = edge_row(e, ei, i2);
    float m = fdec(((unsigned*)(g_S + O_MAX))[row * 4 + h]);
    float ex = expf(g_S[O_LOG + t] - m);
    g_S[O_LOG + t] = ex;
    atomicAdd(&g_S[O_SUM + (size_t)row * 4 + h], ex);
}

// ---------- L1 pass3: recompute eh, scale by alpha, scatter ----------
__global__ void k_l1p3(const int* __restrict__ ei, const int* __restrict__ et,
                       const int* __restrict__ i2) {
    int gt = blockIdx.x * blockDim.x + threadIdx.x;
    int e = gt >> 5, lane = gt & 31;
    if (e >= ET) return;
    int row, col, rt, rt2;
    edge_rc(e, ei, et, i2, row, col, rt, rt2);
    int li = lane * 4;
    const float* PA = g_S + O_PA + (size_t)row * 256;
    const float* PB = g_S + O_PB + (size_t)col * 256;
    const float* PC = g_S + O_PC;
    float4 e0 = f4add(*(const float4*)(PA + li), *(const float4*)(PB + li));
    float4 e1 = f4add(*(const float4*)(PA + 128 + li), *(const float4*)(PB + 128 + li));
    e0 = f4add(e0, *(const float4*)(PC + (size_t)rt * 256 + li));
    e1 = f4add(e1, *(const float4*)(PC + (size_t)rt * 256 + 128 + li));
    if (rt2 >= 0) {
        e0 = f4add(e0, *(const float4*)(PC + (size_t)rt2 * 256 + li));
        e1 = f4add(e1, *(const float4*)(PC + (size_t)rt2 * 256 + 128 + li));
    }
    int ha = lane >> 4;
    float sA = g_S[O_SUM + (size_t)row * 4 + ha];
    float sB = g_S[O_SUM + (size_t)row * 4 + 2 + ha];
    float exA = g_S[O_LOG + (size_t)e * 4 + ha];
    float exB = g_S[O_LOG + (size_t)e * 4 + 2 + ha];
    float alA = exA / (sA + 1e-16f);
    float alB = exB / (sB + 1e-16f);
    float* agg = g_S + O_AGG + (size_t)row * 256;
    atomicAdd(agg + li + 0, e0.x * alA);
    atomicAdd(agg + li + 1, e0.y * alA);
    atomicAdd(agg + li + 2, e0.z * alA);
    atomicAdd(agg + li + 3, e0.w * alA);
    atomicAdd(agg + 128 + li + 0, e1.x * alB);
    atomicAdd(agg + 128 + li + 1, e1.y * alB);
    atomicAdd(agg + 128 + li + 2, e1.z * alB);
    atomicAdd(agg + 128 + li + 3, e1.w * alB);
}

// ---------- x = elu(agg) ----------
__global__ void k_x() {
    size_t i = (size_t)blockIdx.x * blockDim.x + threadIdx.x;
    if (i >= SZ_MAT) return;
    float v = g_S[O_AGG + i];
    g_S[O_X + i] = v > 0.f ? v : expm1f(v);
}

// ---------- L2 pass1: single-head logit + atomic max ----------
__global__ void k_l2p1(const int* __restrict__ ei, const int* __restrict__ et,
                       const int* __restrict__ i2, const float* __restrict__ oa) {
    int gt = blockIdx.x * blockDim.x + threadIdx.x;
    int e = gt >> 5, lane = gt & 31;
    if (e >= ET) return;
    int row, col, rt, rt2;
    edge_rc(e, ei, et, i2, row, col, rt, rt2);
    int li = lane * 4;
    const float* QA = g_S + O_QA + (size_t)row * 256;
    const float* QB = g_S + O_QB + (size_t)col * 256;
    const float* QC = g_S + O_QC;
    float4 e0 = f4add(*(const float4*)(QA + li), *(const float4*)(QB + li));
    float4 e1 = f4add(*(const float4*)(QA + 128 + li), *(const float4*)(QB + 128 + li));
    e0 = f4add(e0, *(const float4*)(QC + (size_t)rt * 256 + li));
    e1 = f4add(e1, *(const float4*)(QC + (size_t)rt * 256 + 128 + li));
    if (rt2 >= 0) {
        e0 = f4add(e0, *(const float4*)(QC + (size_t)rt2 * 256 + li));
        e1 = f4add(e1, *(const float4*)(QC + (size_t)rt2 * 256 + 128 + li));
    }
    float p = dot4(e0, *(const float4*)(oa + li)) +
              dot4(e1, *(const float4*)(oa + 128 + li));
#pragma unroll
    for (int o = 16; o >= 1; o >>= 1) p += __shfl_xor_sync(0xffffffffu, p, o);
    if (lane == 0) {
        float l = p > 0.f ? p : 0.2f * p;
        g_S[O_LOG + e] = l;
        atomicMax(((unsigned*)(g_S + O_MAX)) + row, fenc(l));
    }
}

// ---------- L2 pass2 ----------
__global__ void k_l2p2(const int* __restrict__ ei, const int* __restrict__ i2) {
    int t = blockIdx.x * blockDim.x + threadIdx.x;
    if (t >= ET) return;
    int row = edge_row(t, ei, i2);
    float m = fdec(((unsigned*)(g_S + O_MAX))[row]);
    float ex = expf(g_S[O_LOG + t] - m);
    g_S[O_LOG + t] = ex;
    atomicAdd(&g_S[O_SUM + row], ex);
}

// ---------- L2 pass3 ----------
__global__ void k_l2p3(const int* __restrict__ ei, const int* __restrict__ et,
                       const int* __restrict__ i2) {
    int gt = blockIdx.x * blockDim.x + threadIdx.x;
    int e = gt >> 5, lane = gt & 31;
    if (e >= ET) return;
    int row, col, rt, rt2;
    edge_rc(e, ei, et, i2, row, col, rt, rt2);
    int li = lane * 4;
    const float* QA = g_S + O_QA + (size_t)row * 256;
    const float* QB = g_S + O_QB + (size_t)col * 256;
    const float* QC = g_S + O_QC;
    float4 e0 = f4add(*(const float4*)(QA + li), *(const float4*)(QB + li));
    float4 e1 = f4add(*(const float4*)(QA + 128 + li), *(const float4*)(QB + 128 + li));
    e0 = f4add(e0, *(const float4*)(QC + (size_t)rt * 256 + li));
    e1 = f4add(e1, *(const float4*)(QC + (size_t)rt * 256 + 128 + li));
    if (rt2 >= 0) {
        e0 = f4add(e0, *(const float4*)(QC + (size_t)rt2 * 256 + li));
        e1 = f4add(e1, *(const float4*)(QC + (size_t)rt2 * 256 + 128 + li));
    }
    float s = g_S[O_SUM + row];
    float ex = g_S[O_LOG + e];
    float al = ex / (s + 1e-16f);
    float* agg = g_S + O_AGG + (size_t)row * 256;
    atomicAdd(agg + li + 0, e0.x * al);
    atomicAdd(agg + li + 1, e0.y * al);
    atomicAdd(agg + li + 2, e0.z * al);
    atomicAdd(agg + li + 3, e0.w * al);
    atomicAdd(agg + 128 + li + 0, e1.x * al);
    atomicAdd(agg + 128 + li + 1, e1.y * al);
    atomicAdd(agg + 128 + li + 2, e1.z * al);
    atomicAdd(agg + 128 + li + 3, e1.w * al);
}

// ---------- final: y = elu(out)+ENT, column sums for BN ----------
__global__ void k_fin1() {
    int c = threadIdx.x;  // 256 threads = 256 cols
    float s = 0.f, q = 0.f;
    for (int r = blockIdx.x; r < NE; r += gridDim.x) {
        size_t idx = (size_t)r * 256 + c;
        float v = g_S[O_AGG + idx];
        v = v > 0.f ? v : expm1f(v);
        float y = v + g_S[O_ENT + idx];
        g_S[O_X + idx] = y;
        s += y;
        q += y * y;
    }
    atomicAdd(&g_S[O_CS + c], s);
    atomicAdd(&g_S[O_CQ + c], q);
}

__global__ void k_fin2() {
    int c = threadIdx.x;
    float mu = g_S[O_CS + c] / (float)NE;
    float var = g_S[O_CQ + c] / (float)NE - mu * mu;
    g_S[O_MU + c] = mu;
    g_S[O_RS + c] = rsqrtf(var + 1e-5f);
}

__global__ void k_fin3(float* __restrict__ out, const float* __restrict__ gam,
                       const float* __restrict__ bet) {
    size_t i = (size_t)blockIdx.x * blockDim.x + threadIdx.x;
    if (i >= SZ_MAT) return;
    int c = (int)(i & 255);
    float y = g_S[O_X + i];
    out[i] = (y - g_S[O_MU + c]) * g_S[O_RS + c] * gam[c] + bet[c];
}

// ---------- launcher ----------
extern "C" void kernel_launch(void* const* d_in, const int* in_sizes, int n_in,
                              void* d_out, int out_size) {
    const int*   ei  = (const int*)d_in[0];
    const int*   et  = (const int*)d_in[1];
    const int*   i2  = (const int*)d_in[2];
    const float* emb = (const float*)d_in[3];
    const float* rel = (const float*)d_in[4];
    const float* Wh  = (const float*)d_in[5];
    const float* ah  = (const float*)d_in[6];
    const float* gW  = (const float*)d_in[7];
    const float* oW  = (const float*)d_in[8];
    const float* oa  = (const float*)d_in[9];
    const float* We  = (const float*)d_in[10];
    const float* gam = (const float*)d_in[11];
    const float* bet = (const float*)d_in[12];
    float* out  = (float*)d_out;
    float* rout = out + SZ_MAT;  // r (500x256) stored after x

    float* S = nullptr;
    cudaGetSymbolAddress((void**)&S, g_S);

    const int initBlocks = (int)((SZ_MAT + 255) / 256);
    dim3 gBig(256 / BN, (NE + BM - 1) / BM);
    dim3 gSmall(256 / BN, (NRL + BM - 1) / BM);
    const int ebW = (ET * 32 + 255) / 256;

    k_prep_w<<<128, 256>>>(Wh);
    k_init<<<initBlocks, 256>>>();

    k_gemm<<<gSmall, 256>>>(rel, gW, rout, NRL, 256, 128);             // r
    k_gemm<<<gSmall, 256>>>(rel, S + O_WC, S + O_PC, NRL, 256, 128);   // PC
    k_gemm<<<gBig, 256>>>(emb, S + O_WA, S + O_PA, NE, 256, 128);      // PA
    k_gemm<<<gBig, 256>>>(emb, S + O_WB, S + O_PB, NE, 256, 128);      // PB
    k_gemm<<<gBig, 256>>>(emb, We, S + O_ENT, NE, 256, 128);           // ENT

    k_l1p1<<<ebW, 256>>>(ei, et, i2, ah);
    k_l1p2<<<(ET * 4 + 255) / 256, 256>>>(ei, et, i2);
    k_l1p3<<<ebW, 256>>>(ei, et, i2);
    k_x<<<initBlocks, 256>>>();
    k_init<<<initBlocks, 256>>>();

    k_gemm<<<gBig, 256>>>(S + O_X, oW, S + O_QA, NE, 256, 256);                  // QA
    k_gemm<<<gBig, 256>>>(S + O_X, oW + 256 * 256, S + O_QB, NE, 256, 256);      // QB
    k_gemm<<<gSmall, 256>>>(rout, oW + 512 * 256, S + O_QC, NRL, 256, 256);      // QC

    k_l2p1<<<ebW, 256>>>(ei, et, i2, oa);
    k_l2p2<<<(ET + 255) / 256, 256>>>(ei, i2);
    k_l2p3<<<ebW, 256>>>(ei, et, i2);

    k_fin1<<<512, 256>>>();
    k_fin2<<<1, 256>>>();
    k_fin3<<<initBlocks, 256>>>(out, gam, bet);
}

// round 4
// speedup vs baseline: 1.5447x; 1.5447x over previous
#include <cuda_runtime.h>
#include <math.h>

#define NE 40000
#define NRL 500
#define ED 200000
#define E2 50000
#define ET 250000

static constexpr size_t SZ = (size_t)NE * 256;
static constexpr size_t O_PA  = 0;
static constexpr size_t O_PB  = O_PA + SZ;
static constexpr size_t O_ENT = O_PB + SZ;
static constexpr size_t O_X   = O_ENT + SZ;
static constexpr size_t O_QA  = O_X + SZ;
static constexpr size_t O_QB  = O_QA + SZ;
static constexpr size_t O_PC  = O_QB + SZ;
static constexpr size_t O_QC  = O_PC + (size_t)NRL * 256;
static constexpr size_t O_WA  = O_QC + (size_t)NRL * 256;
static constexpr size_t O_WB  = O_WA + 128 * 256;
static constexpr size_t O_WC  = O_WB + 128 * 256;
static constexpr size_t O_LOG = O_WC + 128 * 256;          // ET*4 floats
static constexpr size_t O_OFF = O_LOG + (size_t)ET * 4;    // NE+1 ints
static constexpr size_t O_CUR = O_OFF + NE + 1;            // NE ints
static constexpr size_t O_SCOL= O_CUR + NE;                // ET ints
static constexpr size_t O_SRT = O_SCOL + ET;
static constexpr size_t O_SRT2= O_SRT + ET;
static constexpr size_t O_CS  = O_SRT2 + ET;
static constexpr size_t O_CQ  = O_CS + 256;
static constexpr size_t O_MU  = O_CQ + 256;
static constexpr size_t O_RS  = O_MU + 256;
static constexpr size_t O_END = O_RS + 256;

__device__ float g_S[O_END];

// ---------------- helpers ----------------
__device__ __forceinline__ float4 f4add(float4 a, float4 b) {
    return make_float4(a.x + b.x, a.y + b.y, a.z + b.z, a.w + b.w);
}
__device__ __forceinline__ float dot4(float4 a, float4 b) {
    return a.x * b.x + a.y * b.y + a.z * b.z + a.w * b.w;
}
__device__ __forceinline__ float eluf(float v) {
    return v > 0.f ? v : expm1f(v);
}
__device__ __forceinline__ unsigned f2tf(float f) {
    unsigned u;
    asm("cvt.rna.tf32.f32 %0, %1;" : "=r"(u) : "f"(f));
    return u;
}

// ---------------- weight repack: W_heads (4,384,64) -> WA/WB/WC (128,256) ----------------
__global__ void k_prep_w(const float* __restrict__ Wh) {
    int t = blockIdx.x * blockDim.x + threadIdx.x;
    if (t >= 128 * 256) return;
    int k = t >> 8, c = t & 255;
    int h = c >> 6, j = c & 63;
    g_S[O_WA + t] = Wh[((h * 384) + k) * 64 + j];
    g_S[O_WB + t] = Wh[((h * 384) + 128 + k) * 64 + j];
    g_S[O_WC + t] = Wh[((h * 384) + 256 + k) * 64 + j];
}

// ---------------- sort edges by row (counting sort) ----------------
__global__ void k_zero() {
    int i = blockIdx.x * blockDim.x + threadIdx.x;
    if (i < NE) ((int*)(g_S + O_CUR))[i] = 0;
    if (i < 256) { g_S[O_CS + i] = 0.f; g_S[O_CQ + i] = 0.f; }
}

__global__ void k_hist(const int* __restrict__ ei, const int* __restrict__ i2) {
    int e = blockIdx.x * blockDim.x + threadIdx.x;
    if (e >= ET) return;
    int row = (e < ED) ? ei[ED + e] : i2[4 * (e - ED) + 3];
    atomicAdd(&((int*)(g_S + O_CUR))[row], 1);
}

__global__ __launch_bounds__(1024) void k_scan() {
    __shared__ int ps[1024];
    int t = threadIdx.x;
    int* cur = (int*)(g_S + O_CUR);
    int* off = (int*)(g_S + O_OFF);
    const int PER = 40;  // 1024*40 >= 40000
    int base = t * PER;
    int s = 0;
    for (int i = 0; i < PER; i++)
        if (base + i < NE) s += cur[base + i];
    ps[t] = s;
    __syncthreads();
    for (int o = 1; o < 1024; o <<= 1) {
        int v = (t >= o) ? ps[t - o] : 0;
        __syncthreads();
        ps[t] += v;
        __syncthreads();
    }
    int run = (t == 0) ? 0 : ps[t - 1];
    for (int i = 0; i < PER; i++) {
        if (base + i < NE) {
            int c = cur[base + i];
            off[base + i] = run;
            cur[base + i] = run;
            run += c;
        }
    }
    if (t == 1023) off[NE] = ET;
}

__global__ void k_scatter(const int* __restrict__ ei, const int* __restrict__ et,
                          const int* __restrict__ i2) {
    int e = blockIdx.x * blockDim.x + threadIdx.x;
    if (e >= ET) return;
    int row, col, rt, rt2;
    if (e < ED) {
        row = ei[ED + e]; col = ei[e]; rt = et[e]; rt2 = -1;
    } else {
        const int* p = i2 + 4 * (e - ED);
        row = p[3]; col = p[0]; rt = p[1]; rt2 = p[2];
    }
    int p2 = atomicAdd(&((int*)(g_S + O_CUR))[row], 1);
    ((int*)(g_S + O_SCOL))[p2] = col;
    ((int*)(g_S + O_SRT))[p2]  = rt;
    ((int*)(g_S + O_SRT2))[p2] = rt2;
}

// ---------------- tf32 tensor-core GEMM: C[M,256] = A[M,K] @ B[K,256] ----------------
__global__ __launch_bounds__(256) void k_gemm_tf32(const float* __restrict__ A,
                                                   const float* __restrict__ B,
                                                   float* __restrict__ C,
                                                   int M, int K) {
    __shared__ unsigned As[128][20];   // stride 20 words -> conflict-free frags
    __shared__ unsigned Bs[16][136];   // stride 136 words -> conflict-free frags
    const int tid = threadIdx.x;
    const int bm = blockIdx.y * 128, bn = blockIdx.x * 128;
    const int w = tid >> 5, lane = tid & 31;
    const int wm = (w >> 1) * 32, wn = (w & 1) * 64;
    const int g = lane >> 2, t = lane & 3;

    float acc[2][8][4];
#pragma unroll
    for (int mi = 0; mi < 2; mi++)
#pragma unroll
        for (int ni = 0; ni < 8; ni++)
#pragma unroll
            for (int q = 0; q < 4; q++) acc[mi][ni][q] = 0.f;

    float4 ra[2], rb[2];
    auto ldA = [&](int k0) {
#pragma unroll
        for (int l = 0; l < 2; l++) {
            int idx = tid + 256 * l;
            int r = idx >> 2, c = (idx & 3) << 2;
            if (bm + r < M)
                ra[l] = *(const float4*)(A + (size_t)(bm + r) * K + k0 + c);
            else
                ra[l] = make_float4(0.f, 0.f, 0.f, 0.f);
        }
    };
    auto ldB = [&](int k0) {
#pragma unroll
        for (int l = 0; l < 2; l++) {
            int idx = tid + 256 * l;
            int r = idx >> 5, c = (idx & 31) << 2;
            rb[l] = *(const float4*)(B + (size_t)(k0 + r) * 256 + bn + c);
        }
    };
    ldA(0); ldB(0);

    for (int k0 = 0; k0 < K; k0 += 16) {
#pragma unroll
        for (int l = 0; l < 2; l++) {
            int idx = tid + 256 * l;
            int r = idx >> 2, c = (idx & 3) << 2;
            uint4 va = make_uint4(f2tf(ra[l].x), f2tf(ra[l].y), f2tf(ra[l].z), f2tf(ra[l].w));
            *(uint4*)&As[r][c] = va;
            int r2 = idx >> 5, c2 = (idx & 31) << 2;
            uint4 vb = make_uint4(f2tf(rb[l].x), f2tf(rb[l].y), f2tf(rb[l].z), f2tf(rb[l].w));
            *(uint4*)&Bs[r2][c2] = vb;
        }
        __syncthreads();
        if (k0 + 16 < K) { ldA(k0 + 16); ldB(k0 + 16); }
#pragma unroll
        for (int kk = 0; kk < 16; kk += 8) {
            unsigned af[2][4];
#pragma unroll
            for (int mi = 0; mi < 2; mi++) {
                int r0 = wm + mi * 16 + g;
                af[mi][0] = As[r0][kk + t];
                af[mi][1] = As[r0 + 8][kk + t];
                af[mi][2] = As[r0][kk + t + 4];
                af[mi][3] = As[r0 + 8][kk + t + 4];
            }
#pragma unroll
            for (int ni = 0; ni < 8; ni++) {
                int cn = wn + ni * 8 + g;
                unsigned b0 = Bs[kk + t][cn], b1 = Bs[kk + t + 4][cn];
#pragma unroll
                for (int mi = 0; mi < 2; mi++) {
                    asm volatile(
                        "mma.sync.aligned.m16n8k8.row.col.f32.tf32.tf32.f32 "
                        "{%0,%1,%2,%3},{%4,%5,%6,%7},{%8,%9},{%0,%1,%2,%3};\n"
                        : "+f"(acc[mi][ni][0]), "+f"(acc[mi][ni][1]),
                          "+f"(acc[mi][ni][2]), "+f"(acc[mi][ni][3])
                        : "r"(af[mi][0]), "r"(af[mi][1]), "r"(af[mi][2]), "r"(af[mi][3]),
                          "r"(b0), "r"(b1));
                }
            }
        }
        __syncthreads();
    }
#pragma unroll
    for (int mi = 0; mi < 2; mi++) {
        int r0 = bm + wm + mi * 16 + g;
#pragma unroll
        for (int ni = 0; ni < 8; ni++) {
            int cn = bn + wn + ni * 8 + 2 * t;
            if (r0 < M)
                *(float2*)(C + (size_t)r0 * 256 + cn) = make_float2(acc[mi][ni][0], acc[mi][ni][1]);
            if (r0 + 8 < M)
                *(float2*)(C + (size_t)(r0 + 8) * 256 + cn) = make_float2(acc[mi][ni][2], acc[mi][ni][3]);
        }
    }
}

// ---------------- layer 1: warp-per-node fused GAT (4 heads) ----------------
__global__ __launch_bounds__(256) void k_layer1(const float* __restrict__ ah) {
    int w = threadIdx.x >> 5, lane = threadIdx.x & 31;
    int n = blockIdx.x * 8 + w;
    if (n >= NE) return;
    const int* off  = (const int*)(g_S + O_OFF);
    const int* scol = (const int*)(g_S + O_SCOL);
    const int* srt  = (const int*)(g_S + O_SRT);
    const int* srt2 = (const int*)(g_S + O_SRT2);
    int s0 = off[n], s1 = off[n + 1];
    int li = lane * 4, ha = lane >> 4;
    const float* PAp = g_S + O_PA + (size_t)n * 256;
    float4 A0 = *(const float4*)(PAp + li);
    float4 A1 = *(const float4*)(PAp + 128 + li);
    float4 av0 = *(const float4*)(ah + ha * 64 + (li & 63));
    float4 av1 = *(const float4*)(ah + (2 + ha) * 64 + (li & 63));
    float sum0 = 0.f, sum1 = 0.f;
    for (int i = s0; i < s1; i++) {
        int col = scol[i], rt = srt[i], rt2 = srt2[i];
        const float* PBp = g_S + O_PB + (size_t)col * 256;
        const float* PCp = g_S + O_PC + (size_t)rt * 256;
        float4 e0 = f4add(f4add(A0, *(const float4*)(PBp + li)), *(const float4*)(PCp + li));
        float4 e1 = f4add(f4add(A1, *(const float4*)(PBp + 128 + li)), *(const float4*)(PCp + 128 + li));
        if (rt2 >= 0) {
            const float* P2 = g_S + O_PC + (size_t)rt2 * 256;
            e0 = f4add(e0, *(const float4*)(P2 + li));
            e1 = f4add(e1, *(const float4*)(P2 + 128 + li));
        }
        float d0 = dot4(e0, av0), d1 = dot4(e1, av1);
#pragma unroll
        for (int o = 8; o >= 1; o >>= 1) {
            d0 += __shfl_xor_sync(0xffffffffu, d0, o);
            d1 += __shfl_xor_sync(0xffffffffu, d1, o);
        }
        d0 = d0 > 0.f ? d0 : 0.2f * d0;
        d1 = d1 > 0.f ? d1 : 0.2f * d1;
        float ex0 = expf(d0), ex1 = expf(d1);
        sum0 += ex0; sum1 += ex1;
        if ((lane & 15) == 0) {
            g_S[O_LOG + (size_t)i * 4 + ha]     = ex0;
            g_S[O_LOG + (size_t)i * 4 + 2 + ha] = ex1;
        }
    }
    float r0 = 1.f / (sum0 + 1e-16f), r1 = 1.f / (sum1 + 1e-16f);
    float4 acc0 = make_float4(0, 0, 0, 0), acc1 = make_float4(0, 0, 0, 0);
    for (int i = s0; i < s1; i++) {
        int col = scol[i], rt = srt[i], rt2 = srt2[i];
        const float* PBp = g_S + O_PB + (size_t)col * 256;
        const float* PCp = g_S + O_PC + (size_t)rt * 256;
        float4 e0 = f4add(f4add(A0, *(const float4*)(PBp + li)), *(const float4*)(PCp + li));
        float4 e1 = f4add(f4add(A1, *(const float4*)(PBp + 128 + li)), *(const float4*)(PCp + 128 + li));
        if (rt2 >= 0) {
            const float* P2 = g_S + O_PC + (size_t)rt2 * 256;
            e0 = f4add(e0, *(const float4*)(P2 + li));
            e1 = f4add(e1, *(const float4*)(P2 + 128 + li));
        }
        float a0 = g_S[O_LOG + (size_t)i * 4 + ha] * r0;
        float a1 = g_S[O_LOG + (size_t)i * 4 + 2 + ha] * r1;
        acc0.x += e0.x * a0; acc0.y += e0.y * a0; acc0.z += e0.z * a0; acc0.w += e0.w * a0;
        acc1.x += e1.x * a1; acc1.y += e1.y * a1; acc1.z += e1.z * a1; acc1.w += e1.w * a1;
    }
    float* Xp = g_S + O_X + (size_t)n * 256;
    Xp[li + 0] = eluf(acc0.x); Xp[li + 1] = eluf(acc0.y);
    Xp[li + 2] = eluf(acc0.z); Xp[li + 3] = eluf(acc0.w);
    Xp[128 + li + 0] = eluf(acc1.x); Xp[128 + li + 1] = eluf(acc1.y);
    Xp[128 + li + 2] = eluf(acc1.z); Xp[128 + li + 3] = eluf(acc1.w);
}

// ---------------- layer 2: warp-per-node fused GAT (1 head) + residual ----------------
__global__ __launch_bounds__(256) void k_layer2(const float* __restrict__ oa) {
    int w = threadIdx.x >> 5, lane = threadIdx.x & 31;
    int n = blockIdx.x * 8 + w;
    if (n >= NE) return;
    const int* off  = (const int*)(g_S + O_OFF);
    const int* scol = (const int*)(g_S + O_SCOL);
    const int* srt  = (const int*)(g_S + O_SRT);
    const int* srt2 = (const int*)(g_S + O_SRT2);
    int s0 = off[n], s1 = off[n + 1];
    int li = lane * 4;
    const float* QAp = g_S + O_QA + (size_t)n * 256;
    float4 A0 = *(const float4*)(QAp + li);
    float4 A1 = *(const float4*)(QAp + 128 + li);
    float4 ov0 = *(const float4*)(oa + li);
    float4 ov1 = *(const float4*)(oa + 128 + li);
    float sum = 0.f;
    for (int i = s0; i < s1; i++) {
        int col = scol[i], rt = srt[i], rt2 = srt2[i];
        const float* QBp = g_S + O_QB + (size_t)col * 256;
        const float* QCp = g_S + O_QC + (size_t)rt * 256;
        float4 e0 = f4add(f4add(A0, *(const float4*)(QBp + li)), *(const float4*)(QCp + li));
        float4 e1 = f4add(f4add(A1, *(const float4*)(QBp + 128 + li)), *(const float4*)(QCp + 128 + li));
        if (rt2 >= 0) {
            const float* P2 = g_S + O_QC + (size_t)rt2 * 256;
            e0 = f4add(e0, *(const float4*)(P2 + li));
            e1 = f4add(e1, *(const float4*)(P2 + 128 + li));
        }
        float d = dot4(e0, ov0) + dot4(e1, ov1);
#pragma unroll
        for (int o = 16; o >= 1; o >>= 1) d += __shfl_xor_sync(0xffffffffu, d, o);
        d = d > 0.f ? d : 0.2f * d;
        float ex = expf(d);
        sum += ex;
        if (lane == 0) g_S[O_LOG + i] = ex;
    }
    float rs = 1.f / (sum + 1e-16f);
    float4 acc0 = make_float4(0, 0, 0, 0), acc1 = make_float4(0, 0, 0, 0);
    for (int i = s0; i < s1; i++) {
        int col = scol[i], rt = srt[i], rt2 = srt2[i];
        const float* QBp = g_S + O_QB + (size_t)col * 256;
        const float* QCp = g_S + O_QC + (size_t)rt * 256;
        float4 e0 = f4add(f4add(A0, *(const float4*)(QBp + li)), *(const float4*)(QCp + li));
        float4 e1 = f4add(f4add(A1, *(const float4*)(QBp + 128 + li)), *(const float4*)(QCp + 128 + li));
        if (rt2 >= 0) {
            const float* P2 = g_S + O_QC + (size_t)rt2 * 256;
            e0 = f4add(e0, *(const float4*)(P2 + li));
            e1 = f4add(e1, *(const float4*)(P2 + 128 + li));
        }
        float a = g_S[O_LOG + i] * rs;
        acc0.x += e0.x * a; acc0.y += e0.y * a; acc0.z += e0.z * a; acc0.w += e0.w * a;
        acc1.x += e1.x * a; acc1.y += e1.y * a; acc1.z += e1.z * a; acc1.w += e1.w * a;
    }
    const float* Ep = g_S + O_ENT + (size_t)n * 256;
    float* Xp = g_S + O_X + (size_t)n * 256;  // overwrite X with y (QA/QB already built)
    Xp[li + 0] = eluf(acc0.x) + Ep[li + 0];
    Xp[li + 1] = eluf(acc0.y) + Ep[li + 1];
    Xp[li + 2] = eluf(acc0.z) + Ep[li + 2];
    Xp[li + 3] = eluf(acc0.w) + Ep[li + 3];
    Xp[128 + li + 0] = eluf(acc1.x) + Ep[128 + li + 0];
    Xp[128 + li + 1] = eluf(acc1.y) + Ep[128 + li + 1];
    Xp[128 + li + 2] = eluf(acc1.z) + Ep[128 + li + 2];
    Xp[128 + li + 3] = eluf(acc1.w) + Ep[128 + li + 3];
}

// ---------------- BN ----------------
__global__ void k_fin1() {
    int c = threadIdx.x;
    float s = 0.f, q = 0.f;
    for (int r = blockIdx.x; r < NE; r += gridDim.x) {
        float y = g_S[O_X + (size_t)r * 256 + c];
        s += y; q += y * y;
    }
    atomicAdd(&g_S[O_CS + c], s);
    atomicAdd(&g_S[O_CQ + c], q);
}

__global__ void k_fin2() {
    int c = threadIdx.x;
    float mu = g_S[O_CS + c] / (float)NE;
    float var = g_S[O_CQ + c] / (float)NE - mu * mu;
    g_S[O_MU + c] = mu;
    g_S[O_RS + c] = rsqrtf(var + 1e-5f);
}

__global__ void k_fin3(float* __restrict__ out, const float* __restrict__ gam,
                       const float* __restrict__ bet) {
    size_t i = (size_t)blockIdx.x * blockDim.x + threadIdx.x;
    if (i >= SZ) return;
    int c = (int)(i & 255);
    float y = g_S[O_X + i];
    out[i] = (y - g_S[O_MU + c]) * g_S[O_RS + c] * gam[c] + bet[c];
}

// ---------------- launcher ----------------
extern "C" void kernel_launch(void* const* d_in, const int* in_sizes, int n_in,
                              void* d_out, int out_size) {
    const int*   ei  = (const int*)d_in[0];
    const int*   et  = (const int*)d_in[1];
    const int*   i2  = (const int*)d_in[2];
    const float* emb = (const float*)d_in[3];
    const float* rel = (const float*)d_in[4];
    const float* Wh  = (const float*)d_in[5];
    const float* ah  = (const float*)d_in[6];
    const float* gW  = (const float*)d_in[7];
    const float* oW  = (const float*)d_in[8];
    const float* oa  = (const float*)d_in[9];
    const float* We  = (const float*)d_in[10];
    const float* gam = (const float*)d_in[11];
    const float* bet = (const float*)d_in[12];
    float* out  = (float*)d_out;
    float* rout = out + SZ;  // r (500x256)

    float* S = nullptr;
    cudaGetSymbolAddress((void**)&S, g_S);

    const int eb = (ET + 255) / 256;
    dim3 gBig(2, (NE + 127) / 128);
    dim3 gSmall(2, (NRL + 127) / 128);

    k_prep_w<<<128, 256>>>(Wh);
    k_zero<<<(NE + 255) / 256, 256>>>();
    k_hist<<<eb, 256>>>(ei, i2);
    k_scan<<<1, 1024>>>();
    k_scatter<<<eb, 256>>>(ei, et, i2);

    k_gemm_tf32<<<gSmall, 256>>>(rel, gW, rout, NRL, 128);            // r
    k_gemm_tf32<<<gSmall, 256>>>(rel, S + O_WC, S + O_PC, NRL, 128);  // PC
    k_gemm_tf32<<<gBig, 256>>>(emb, S + O_WA, S + O_PA, NE, 128);     // PA
    k_gemm_tf32<<<gBig, 256>>>(emb, S + O_WB, S + O_PB, NE, 128);     // PB
    k_gemm_tf32<<<gBig, 256>>>(emb, We, S + O_ENT, NE, 128);          // ENT

    k_layer1<<<(NE + 7) / 8, 256>>>(ah);

    k_gemm_tf32<<<gBig, 256>>>(S + O_X, oW, S + O_QA, NE, 256);                // QA
    k_gemm_tf32<<<gBig, 256>>>(S + O_X, oW + 256 * 256, S + O_QB, NE, 256);    // QB
    k_gemm_tf32<<<gSmall, 256>>>(rout, oW + 512 * 256, S + O_QC, NRL, 256);    // QC

    k_layer2<<<(NE + 7) / 8, 256>>>(oa);

    k_fin1<<<512, 256>>>();
    k_fin2<<<1, 256>>>();
    k_fin3<<<(int)((SZ + 255) / 256), 256>>>(out, gam, bet);
}

// round 6
// speedup vs baseline: 2.5190x; 1.6308x over previous
#include <cuda_runtime.h>
#include <math.h>

#define NE 40000
#define NRL 500
#define ED 200000
#define E2 50000
#define ET 250000

static constexpr size_t SZ = (size_t)NE * 256;
// PA,PB,ENT consecutive (fused GEMM-1 C stride = SZ)
static constexpr size_t O_PA  = 0;
static constexpr size_t O_PB  = O_PA + SZ;
static constexpr size_t O_ENT = O_PB + SZ;
static constexpr size_t O_X   = O_ENT + SZ;
// QA,QB consecutive (fused GEMM-2 C stride = SZ)
static constexpr size_t O_QA  = O_X + SZ;
static constexpr size_t O_QB  = O_QA + SZ;
static constexpr size_t O_PC  = O_QB + SZ;
static constexpr size_t O_QC  = O_PC + (size_t)NRL * 256;
// WA,WB,WE consecutive (fused GEMM-1 B stride = 128*256)
static constexpr size_t O_WA  = O_QC + (size_t)NRL * 256;
static constexpr size_t O_WB  = O_WA + 128 * 256;
static constexpr size_t O_WE  = O_WB + 128 * 256;
static constexpr size_t O_WC  = O_WE + 128 * 256;
static constexpr size_t O_BS  = O_WC + 128 * 256;          // 256 ints (block sums)
static constexpr size_t O_OFF = O_BS + 256;                // NE+1 ints
static constexpr size_t O_CUR = O_OFF + NE + 1;            // NE ints
static constexpr size_t O_SCOL= O_CUR + NE;                // ET ints
static constexpr size_t O_SRT = O_SCOL + ET;
static constexpr size_t O_SRT2= O_SRT + ET;
static constexpr size_t O_CS  = O_SRT2 + ET;
static constexpr size_t O_CQ  = O_CS + 256;
static constexpr size_t O_MU  = O_CQ + 256;
static constexpr size_t O_RS  = O_MU + 256;
static constexpr size_t O_END = O_RS + 256;

__device__ float g_S[O_END];

static constexpr int SCAN_NB = (NE + 255) / 256;  // 157

// ---------------- helpers ----------------
__device__ __forceinline__ float4 f4add(float4 a, float4 b) {
    return make_float4(a.x + b.x, a.y + b.y, a.z + b.z, a.w + b.w);
}
__device__ __forceinline__ float dot4(float4 a, float4 b) {
    return a.x * b.x + a.y * b.y + a.z * b.z + a.w * b.w;
}
__device__ __forceinline__ float eluf(float v) {
    return v > 0.f ? v : expm1f(v);
}
__device__ __forceinline__ unsigned f2tf(float f) {
    unsigned u;
    asm("cvt.rna.tf32.f32 %0, %1;" : "=r"(u) : "f"(f));
    return u;
}

// ---------------- weight repack + We copy ----------------
__global__ void k_prep_w(const float* __restrict__ Wh, const float* __restrict__ We) {
    int t = blockIdx.x * blockDim.x + threadIdx.x;
    if (t >= 128 * 256) return;
    int k = t >> 8, c = t & 255;
    int h = c >> 6, j = c & 63;
    g_S[O_WA + t] = Wh[((h * 384) + k) * 64 + j];
    g_S[O_WB + t] = Wh[((h * 384) + 128 + k) * 64 + j];
    g_S[O_WC + t] = Wh[((h * 384) + 256 + k) * 64 + j];
    g_S[O_WE + t] = We[t];
}

// ---------------- counting sort: hist + 3-step parallel scan + scatter ----------------
__global__ void k_zero() {
    int i = blockIdx.x * blockDim.x + threadIdx.x;
    if (i < NE) ((int*)(g_S + O_CUR))[i] = 0;
    if (i < 256) { g_S[O_CS + i] = 0.f; g_S[O_CQ + i] = 0.f; }
}

__global__ void k_hist(const int* __restrict__ ei, const int* __restrict__ i2) {
    int e = blockIdx.x * blockDim.x + threadIdx.x;
    if (e >= ET) return;
    int row = (e < ED) ? ei[ED + e] : i2[4 * (e - ED) + 3];
    atomicAdd(&((int*)(g_S + O_CUR))[row], 1);
}

// per-block partial sums
__global__ __launch_bounds__(256) void k_scan1() {
    __shared__ int sm[256];
    int idx = blockIdx.x * 256 + threadIdx.x;
    int v = (idx < NE) ? ((int*)(g_S + O_CUR))[idx] : 0;
    sm[threadIdx.x] = v;
    __syncthreads();
#pragma unroll
    for (int o = 128; o >= 1; o >>= 1) {
        if (threadIdx.x < o) sm[threadIdx.x] += sm[threadIdx.x + o];
        __syncthreads();
    }
    if (threadIdx.x == 0) ((int*)(g_S + O_BS))[blockIdx.x] = sm[0];
}

// spine: exclusive scan of 157 block sums
__global__ __launch_bounds__(256) void k_scan2() {
    __shared__ int sm[256];
    int t = threadIdx.x;
    int* bs = (int*)(g_S + O_BS);
    int v = (t < SCAN_NB) ? bs[t] : 0;
    sm[t] = v;
    __syncthreads();
#pragma unroll
    for (int o = 1; o < 256; o <<= 1) {
        int u = (t >= o) ? sm[t - o] : 0;
        __syncthreads();
        sm[t] += u;
        __syncthreads();
    }
    if (t < SCAN_NB) bs[t] = sm[t] - v;  // exclusive
    if (t == 0) ((int*)(g_S + O_OFF))[NE] = ET;
}

// local exclusive scan + write offsets
__global__ __launch_bounds__(256) void k_scan3() {
    __shared__ int sm[256];
    int t = threadIdx.x;
    int idx = blockIdx.x * 256 + t;
    int* cur = (int*)(g_S + O_CUR);
    int* off = (int*)(g_S + O_OFF);
    int c = (idx < NE) ? cur[idx] : 0;
    sm[t] = c;
    __syncthreads();
#pragma unroll
    for (int o = 1; o < 256; o <<= 1) {
        int u = (t >= o) ? sm[t - o] : 0;
        __syncthreads();
        sm[t] += u;
        __syncthreads();
    }
    int base = ((int*)(g_S + O_BS))[blockIdx.x];
    if (idx < NE) {
        int v = base + sm[t] - c;
        off[idx] = v;
        cur[idx] = v;
    }
}

__global__ void k_scatter(const int* __restrict__ ei, const int* __restrict__ et,
                          const int* __restrict__ i2) {
    int e = blockIdx.x * blockDim.x + threadIdx.x;
    if (e >= ET) return;
    int row, col, rt, rt2;
    if (e < ED) {
        row = ei[ED + e]; col = ei[e]; rt = et[e]; rt2 = -1;
    } else {
        const int* p = i2 + 4 * (e - ED);
        row = p[3]; col = p[0]; rt = p[1]; rt2 = p[2];
    }
    int p2 = atomicAdd(&((int*)(g_S + O_CUR))[row], 1);
    ((int*)(g_S + O_SCOL))[p2] = col;
    ((int*)(g_S + O_SRT))[p2]  = rt;
    ((int*)(g_S + O_SRT2))[p2] = rt2;
}

// ---------------- tf32 tensor-core GEMM, multi-matrix batched over shared A ----------------
// C_mat[M,256] = A[M,K] @ B_mat[K,256];  mat = blockIdx.x>>1, col-tile = blockIdx.x&1
__global__ __launch_bounds__(256) void k_gemm_tf32(const float* __restrict__ A,
                                                   const float* __restrict__ Bb,
                                                   float* __restrict__ Cb,
                                                   int M, int K,
                                                   int bStride, long long cStride) {
    __shared__ unsigned As[128][20];
    __shared__ unsigned Bs[16][136];
    const int tid = threadIdx.x;
    const int mat = blockIdx.x >> 1;
    const float* B = Bb + (size_t)mat * bStride;
    float* C = Cb + (size_t)mat * cStride;
    const int bm = blockIdx.y * 128, bn = (blockIdx.x & 1) * 128;
    const int w = tid >> 5, lane = tid & 31;
    const int wm = (w >> 1) * 32, wn = (w & 1) * 64;
    const int g = lane >> 2, t = lane & 3;

    float acc[2][8][4];
#pragma unroll
    for (int mi = 0; mi < 2; mi++)
#pragma unroll
        for (int ni = 0; ni < 8; ni++)
#pragma unroll
            for (int q = 0; q < 4; q++) acc[mi][ni][q] = 0.f;

    float4 ra[2], rb[2];
    auto ldA = [&](int k0) {
#pragma unroll
        for (int l = 0; l < 2; l++) {
            int idx = tid + 256 * l;
            int r = idx >> 2, c = (idx & 3) << 2;
            if (bm + r < M)
                ra[l] = *(const float4*)(A + (size_t)(bm + r) * K + k0 + c);
            else
                ra[l] = make_float4(0.f, 0.f, 0.f, 0.f);
        }
    };
    auto ldB = [&](int k0) {
#pragma unroll
        for (int l = 0; l < 2; l++) {
            int idx = tid + 256 * l;
            int r = idx >> 5, c = (idx & 31) << 2;
            rb[l] = *(const float4*)(B + (size_t)(k0 + r) * 256 + bn + c);
        }
    };
    ldA(0); ldB(0);

    for (int k0 = 0; k0 < K; k0 += 16) {
#pragma unroll
        for (int l = 0; l < 2; l++) {
            int idx = tid + 256 * l;
            int r = idx >> 2, c = (idx & 3) << 2;
            uint4 va = make_uint4(f2tf(ra[l].x), f2tf(ra[l].y), f2tf(ra[l].z), f2tf(ra[l].w));
            *(uint4*)&As[r][c] = va;
            int r2 = idx >> 5, c2 = (idx & 31) << 2;
            uint4 vb = make_uint4(f2tf(rb[l].x), f2tf(rb[l].y), f2tf(rb[l].z), f2tf(rb[l].w));
            *(uint4*)&Bs[r2][c2] = vb;
        }
        __syncthreads();
        if (k0 + 16 < K) { ldA(k0 + 16); ldB(k0 + 16); }
#pragma unroll
        for (int kk = 0; kk < 16; kk += 8) {
            unsigned af[2][4];
#pragma unroll
            for (int mi = 0; mi < 2; mi++) {
                int r0 = wm + mi * 16 + g;
                af[mi][0] = As[r0][kk + t];
                af[mi][1] = As[r0 + 8][kk + t];
                af[mi][2] = As[r0][kk + t + 4];
                af[mi][3] = As[r0 + 8][kk + t + 4];
            }
#pragma unroll
            for (int ni = 0; ni < 8; ni++) {
                int cn = wn + ni * 8 + g;
                unsigned b0 = Bs[kk + t][cn], b1 = Bs[kk + t + 4][cn];
#pragma unroll
                for (int mi = 0; mi < 2; mi++) {
                    asm volatile(
                        "mma.sync.aligned.m16n8k8.row.col.f32.tf32.tf32.f32 "
                        "{%0,%1,%2,%3},{%4,%5,%6,%7},{%8,%9},{%0,%1,%2,%3};\n"
                        : "+f"(acc[mi][ni][0]), "+f"(acc[mi][ni][1]),
                          "+f"(acc[mi][ni][2]), "+f"(acc[mi][ni][3])
                        : "r"(af[mi][0]), "r"(af[mi][1]), "r"(af[mi][2]), "r"(af[mi][3]),
                          "r"(b0), "r"(b1));
                }
            }
        }
        __syncthreads();
    }
#pragma unroll
    for (int mi = 0; mi < 2; mi++) {
        int r0 = bm + wm + mi * 16 + g;
#pragma unroll
        for (int ni = 0; ni < 8; ni++) {
            int cn = bn + wn + ni * 8 + 2 * t;
            if (r0 < M)
                *(float2*)(C + (size_t)r0 * 256 + cn) = make_float2(acc[mi][ni][0], acc[mi][ni][1]);
            if (r0 + 8 < M)
                *(float2*)(C + (size_t)(r0 + 8) * 256 + cn) = make_float2(acc[mi][ni][2], acc[mi][ni][3]);
        }
    }
}

// ---------------- layer 1: warp-per-node, SINGLE PASS (4 heads) ----------------
__global__ __launch_bounds__(256) void k_layer1(const float* __restrict__ ah) {
    int w = threadIdx.x >> 5, lane = threadIdx.x & 31;
    int n = blockIdx.x * 8 + w;
    if (n >= NE) return;
    const int* off  = (const int*)(g_S + O_OFF);
    const int* scol = (const int*)(g_S + O_SCOL);
    const int* srt  = (const int*)(g_S + O_SRT);
    const int* srt2 = (const int*)(g_S + O_SRT2);
    int s0 = off[n], s1 = off[n + 1];
    int li = lane * 4, ha = lane >> 4;
    const float* PAp = g_S + O_PA + (size_t)n * 256;
    float4 A0 = *(const float4*)(PAp + li);
    float4 A1 = *(const float4*)(PAp + 128 + li);
    float4 av0 = *(const float4*)(ah + ha * 64 + (li & 63));
    float4 av1 = *(const float4*)(ah + (2 + ha) * 64 + (li & 63));
    float sum0 = 0.f, sum1 = 0.f;
    float4 acc0 = make_float4(0, 0, 0, 0), acc1 = make_float4(0, 0, 0, 0);
    for (int i = s0; i < s1; i++) {
        int col = scol[i], rt = srt[i], rt2 = srt2[i];
        const float* PBp = g_S + O_PB + (size_t)col * 256;
        const float* PCp = g_S + O_PC + (size_t)rt * 256;
        float4 e0 = f4add(f4add(A0, *(const float4*)(PBp + li)), *(const float4*)(PCp + li));
        float4 e1 = f4add(f4add(A1, *(const float4*)(PBp + 128 + li)), *(const float4*)(PCp + 128 + li));
        if (rt2 >= 0) {
            const float* P2 = g_S + O_PC + (size_t)rt2 * 256;
            e0 = f4add(e0, *(const float4*)(P2 + li));
            e1 = f4add(e1, *(const float4*)(P2 + 128 + li));
        }
        float d0 = dot4(e0, av0), d1 = dot4(e1, av1);
#pragma unroll
        for (int o = 8; o >= 1; o >>= 1) {
            d0 += __shfl_xor_sync(0xffffffffu, d0, o);
            d1 += __shfl_xor_sync(0xffffffffu, d1, o);
        }
        d0 = d0 > 0.f ? d0 : 0.2f * d0;
        d1 = d1 > 0.f ? d1 : 0.2f * d1;
        float ex0 = expf(d0), ex1 = expf(d1);
        sum0 += ex0; sum1 += ex1;
        acc0.x += e0.x * ex0; acc0.y += e0.y * ex0; acc0.z += e0.z * ex0; acc0.w += e0.w * ex0;
        acc1.x += e1.x * ex1; acc1.y += e1.y * ex1; acc1.z += e1.z * ex1; acc1.w += e1.w * ex1;
    }
    float r0 = 1.f / (sum0 + 1e-16f), r1 = 1.f / (sum1 + 1e-16f);
    float* Xp = g_S + O_X + (size_t)n * 256;
    Xp[li + 0] = eluf(acc0.x * r0); Xp[li + 1] = eluf(acc0.y * r0);
    Xp[li + 2] = eluf(acc0.z * r0); Xp[li + 3] = eluf(acc0.w * r0);
    Xp[128 + li + 0] = eluf(acc1.x * r1); Xp[128 + li + 1] = eluf(acc1.y * r1);
    Xp[128 + li + 2] = eluf(acc1.z * r1); Xp[128 + li + 3] = eluf(acc1.w * r1);
}

// ---------------- layer 2: warp-per-node, SINGLE PASS (1 head) + residual ----------------
__global__ __launch_bounds__(256) void k_layer2(const float* __restrict__ oa) {
    int w = threadIdx.x >> 5, lane = threadIdx.x & 31;
    int n = blockIdx.x * 8 + w;
    if (n >= NE) return;
    const int* off  = (const int*)(g_S + O_OFF);
    const int* scol = (const int*)(g_S + O_SCOL);
    const int* srt  = (const int*)(g_S + O_SRT);
    const int* srt2 = (const int*)(g_S + O_SRT2);
    int s0 = off[n], s1 = off[n + 1];
    int li = lane * 4;
    const float* QAp = g_S + O_QA + (size_t)n * 256;
    float4 A0 = *(const float4*)(QAp + li);
    float4 A1 = *(const float4*)(QAp + 128 + li);
    float4 ov0 = *(const float4*)(oa + li);
    float4 ov1 = *(const float4*)(oa + 128 + li);
    float sum = 0.f;
    float4 acc0 = make_float4(0, 0, 0, 0), acc1 = make_float4(0, 0, 0, 0);
    for (int i = s0; i < s1; i++) {
        int col = scol[i], rt = srt[i], rt2 = srt2[i];
        const float* QBp = g_S + O_QB + (size_t)col * 256;
        const float* QCp = g_S + O_QC + (size_t)rt * 256;
        float4 e0 = f4add(f4add(A0, *(const float4*)(QBp + li)), *(const float4*)(QCp + li));
        float4 e1 = f4add(f4add(A1, *(const float4*)(QBp + 128 + li)), *(const float4*)(QCp + 128 + li));
        if (rt2 >= 0) {
            const float* P2 = g_S + O_QC + (size_t)rt2 * 256;
            e0 = f4add(e0, *(const float4*)(P2 + li));
            e1 = f4add(e1, *(const float4*)(P2 + 128 + li));
        }
        float d = dot4(e0, ov0) + dot4(e1, ov1);
#pragma unroll
        for (int o = 16; o >= 1; o >>= 1) d += __shfl_xor_sync(0xffffffffu, d, o);
        d = d > 0.f ? d : 0.2f * d;
        float ex = expf(d);
        sum += ex;
        acc0.x += e0.x * ex; acc0.y += e0.y * ex; acc0.z += e0.z * ex; acc0.w += e0.w * ex;
        acc1.x += e1.x * ex; acc1.y += e1.y * ex; acc1.z += e1.z * ex; acc1.w += e1.w * ex;
    }
    float rs = 1.f / (sum + 1e-16f);
    const float* Ep = g_S + O_ENT + (size_t)n * 256;
    float* Xp = g_S + O_X + (size_t)n * 256;
    Xp[li + 0] = eluf(acc0.x * rs) + Ep[li + 0];
    Xp[li + 1] = eluf(acc0.y * rs) + Ep[li + 1];
    Xp[li + 2] = eluf(acc0.z * rs) + Ep[li + 2];
    Xp[li + 3] = eluf(acc0.w * rs) + Ep[li + 3];
    Xp[128 + li + 0] = eluf(acc1.x * rs) + Ep[128 + li + 0];
    Xp[128 + li + 1] = eluf(acc1.y * rs) + Ep[128 + li + 1];
    Xp[128 + li + 2] = eluf(acc1.z * rs) + Ep[128 + li + 2];
    Xp[128 + li + 3] = eluf(acc1.w * rs) + Ep[128 + li + 3];
}

// ---------------- BN ----------------
__global__ void k_fin1() {
    int c = threadIdx.x;
    float s = 0.f, q = 0.f;
    for (int r = blockIdx.x; r < NE; r += gridDim.x) {
        float y = g_S[O_X + (size_t)r * 256 + c];
        s += y; q += y * y;
    }
    atomicAdd(&g_S[O_CS + c], s);
    atomicAdd(&g_S[O_CQ + c], q);
}

__global__ void k_fin2() {
    int c = threadIdx.x;
    float mu = g_S[O_CS + c] / (float)NE;
    float var = g_S[O_CQ + c] / (float)NE - mu * mu;
    g_S[O_MU + c] = mu;
    g_S[O_RS + c] = rsqrtf(var + 1e-5f);
}

__global__ void k_fin3(float* __restrict__ out, const float* __restrict__ gam,
                       const float* __restrict__ bet) {
    size_t i = (size_t)blockIdx.x * blockDim.x + threadIdx.x;
    if (i >= SZ) return;
    int c = (int)(i & 255);
    float y = g_S[O_X + i];
    out[i] = (y - g_S[O_MU + c]) * g_S[O_RS + c] * gam[c] + bet[c];
}

// ---------------- launcher ----------------
extern "C" void kernel_launch(void* const* d_in, const int* in_sizes, int n_in,
                              void* d_out, int out_size) {
    const int*   ei  = (const int*)d_in[0];
    const int*   et  = (const int*)d_in[1];
    const int*   i2  = (const int*)d_in[2];
    const float* emb = (const float*)d_in[3];
    const float* rel = (const float*)d_in[4];
    const float* Wh  = (const float*)d_in[5];
    const float* ah  = (const float*)d_in[6];
    const float* gW  = (const float*)d_in[7];
    const float* oW  = (const float*)d_in[8];
    const float* oa  = (const float*)d_in[9];
    const float* We  = (const float*)d_in[10];
    const float* gam = (const float*)d_in[11];
    const float* bet = (const float*)d_in[12];
    float* out  = (float*)d_out;
    float* rout = out + SZ;  // r (500x256)

    float* S = nullptr;
    cudaGetSymbolAddress((void**)&S, g_S);

    const int eb = (ET + 255) / 256;

    k_prep_w<<<128, 256>>>(Wh, We);
    k_zero<<<(NE + 255) / 256, 256>>>();
    k_hist<<<eb, 256>>>(ei, i2);
    k_scan1<<<SCAN_NB, 256>>>();
    k_scan2<<<1, 256>>>();
    k_scan3<<<SCAN_NB, 256>>>();
    k_scatter<<<eb, 256>>>(ei, et, i2);

    // small GEMMs (single-matrix each)
    dim3 gSmall(2, (NRL + 127) / 128);
    k_gemm_tf32<<<gSmall, 256>>>(rel, gW, rout, NRL, 128, 0, 0);              // r
    k_gemm_tf32<<<gSmall, 256>>>(rel, S + O_WC, S + O_PC, NRL, 128, 0, 0);    // PC

    // fused GEMM-1: PA,PB,ENT = emb @ {WA,WB,WE}
    dim3 gBig1(6, (NE + 127) / 128);
    k_gemm_tf32<<<gBig1, 256>>>(emb, S + O_WA, S + O_PA, NE, 128,
                                128 * 256, (long long)SZ);

    k_layer1<<<(NE + 7) / 8, 256>>>(ah);

    // fused GEMM-2: QA,QB = X @ {oW0,oW1}
    dim3 gBig2(4, (NE + 127) / 128);
    k_gemm_tf32<<<gBig2, 256>>>(S + O_X, oW, S + O_QA, NE, 256,
                                256 * 256, (long long)SZ);
    k_gemm_tf32<<<gSmall, 256>>>(rout, oW + 512 * 256, S + O_QC, NRL, 256, 0, 0);  // QC

    k_layer2<<<(NE + 7) / 8, 256>>>(oa);

    k_fin1<<<512, 256>>>();
    k_fin2<<<1, 256>>>();
    k_fin3<<<(int)((SZ + 255) / 256), 256>>>(out, gam, bet);
}

// round 7
// speedup vs baseline: 2.5922x; 1.0290x over previous
#include <cuda_runtime.h>
#include <math.h>

#define NE 40000
#define NRL 500
#define ED 200000
#define E2 50000
#define ET 250000

static constexpr size_t SZ = (size_t)NE * 256;
static constexpr size_t O_PA  = 0;
static constexpr size_t O_PB  = O_PA + SZ;
static constexpr size_t O_ENT = O_PB + SZ;
static constexpr size_t O_X   = O_ENT + SZ;
static constexpr size_t O_QA  = O_X + SZ;
static constexpr size_t O_QB  = O_QA + SZ;
static constexpr size_t O_PC  = O_QB + SZ;
static constexpr size_t O_QC  = O_PC + (size_t)NRL * 256;
static constexpr size_t O_WA  = O_QC + (size_t)NRL * 256;
static constexpr size_t O_WB  = O_WA + 128 * 256;
static constexpr size_t O_WE  = O_WB + 128 * 256;
static constexpr size_t O_WC  = O_WE + 128 * 256;
static constexpr size_t O_BS  = O_WC + 128 * 256;          // 256 ints
static constexpr size_t O_OFF = O_BS + 256;                // NE+4 ints (padded)
static constexpr size_t O_CUR = O_OFF + NE + 4;            // NE ints
static constexpr size_t O_SPK = O_CUR + NE;                // ET int4 records
static constexpr size_t O_CS  = O_SPK + (size_t)ET * 4;
static constexpr size_t O_CQ  = O_CS + 256;
static constexpr size_t O_MU  = O_CQ + 256;
static constexpr size_t O_RS  = O_MU + 256;
static constexpr size_t O_END = O_RS + 256;

__device__ float g_S[O_END];

static constexpr int SCAN_NB = (NE + 255) / 256;  // 157

// ---------------- helpers ----------------
__device__ __forceinline__ float4 f4add(float4 a, float4 b) {
    return make_float4(a.x + b.x, a.y + b.y, a.z + b.z, a.w + b.w);
}
__device__ __forceinline__ float dot4(float4 a, float4 b) {
    return a.x * b.x + a.y * b.y + a.z * b.z + a.w * b.w;
}
__device__ __forceinline__ float eluf(float v) {
    return v > 0.f ? v : expm1f(v);
}
__device__ __forceinline__ float lrelu(float v) {
    return v > 0.f ? v : 0.2f * v;
}
__device__ __forceinline__ unsigned f2tf(float f) {
    unsigned u;
    asm("cvt.rna.tf32.f32 %0, %1;" : "=r"(u) : "f"(f));
    return u;
}

// ---------------- weight repack + We copy ----------------
__global__ void k_prep_w(const float* __restrict__ Wh, const float* __restrict__ We) {
    int t = blockIdx.x * blockDim.x + threadIdx.x;
    if (t >= 128 * 256) return;
    int k = t >> 8, c = t & 255;
    int h = c >> 6, j = c & 63;
    g_S[O_WA + t] = Wh[((h * 384) + k) * 64 + j];
    g_S[O_WB + t] = Wh[((h * 384) + 128 + k) * 64 + j];
    g_S[O_WC + t] = Wh[((h * 384) + 256 + k) * 64 + j];
    g_S[O_WE + t] = We[t];
}

// ---------------- counting sort ----------------
__global__ void k_zero() {
    int i = blockIdx.x * blockDim.x + threadIdx.x;
    if (i < NE) ((int*)(g_S + O_CUR))[i] = 0;
    if (i < 256) { g_S[O_CS + i] = 0.f; g_S[O_CQ + i] = 0.f; }
}

__global__ void k_hist(const int* __restrict__ ei, const int* __restrict__ i2) {
    int e = blockIdx.x * blockDim.x + threadIdx.x;
    if (e >= ET) return;
    int row = (e < ED) ? ei[ED + e] : i2[4 * (e - ED) + 3];
    atomicAdd(&((int*)(g_S + O_CUR))[row], 1);
}

__global__ __launch_bounds__(256) void k_scan1() {
    __shared__ int ws[8];
    int idx = blockIdx.x * 256 + threadIdx.x;
    int lane = threadIdx.x & 31, w = threadIdx.x >> 5;
    int v = (idx < NE) ? ((int*)(g_S + O_CUR))[idx] : 0;
#pragma unroll
    for (int o = 16; o >= 1; o >>= 1) v += __shfl_xor_sync(0xffffffffu, v, o);
    if (lane == 0) ws[w] = v;
    __syncthreads();
    if (threadIdx.x == 0) {
        int s = 0;
#pragma unroll
        for (int j = 0; j < 8; j++) s += ws[j];
        ((int*)(g_S + O_BS))[blockIdx.x] = s;
    }
}

__global__ __launch_bounds__(256) void k_scan2() {
    __shared__ int sm[256];
    int t = threadIdx.x;
    int* bs = (int*)(g_S + O_BS);
    int v = (t < SCAN_NB) ? bs[t] : 0;
    sm[t] = v;
    __syncthreads();
#pragma unroll
    for (int o = 1; o < 256; o <<= 1) {
        int u = (t >= o) ? sm[t - o] : 0;
        __syncthreads();
        sm[t] += u;
        __syncthreads();
    }
    if (t < SCAN_NB) bs[t] = sm[t] - v;  // exclusive
    if (t == 0) ((int*)(g_S + O_OFF))[NE] = ET;
}

__global__ __launch_bounds__(256) void k_scan3() {
    __shared__ int sm[256];
    int t = threadIdx.x;
    int idx = blockIdx.x * 256 + t;
    int* cur = (int*)(g_S + O_CUR);
    int* off = (int*)(g_S + O_OFF);
    int c = (idx < NE) ? cur[idx] : 0;
    sm[t] = c;
    __syncthreads();
#pragma unroll
    for (int o = 1; o < 256; o <<= 1) {
        int u = (t >= o) ? sm[t - o] : 0;
        __syncthreads();
        sm[t] += u;
        __syncthreads();
    }
    int base = ((int*)(g_S + O_BS))[blockIdx.x];
    if (idx < NE) {
        int v = base + sm[t] - c;
        off[idx] = v;
        cur[idx] = v;
    }
}

__global__ void k_scatter(const int* __restrict__ ei, const int* __restrict__ et,
                          const int* __restrict__ i2) {
    int e = blockIdx.x * blockDim.x + threadIdx.x;
    if (e >= ET) return;
    int row, col, rt, rt2;
    if (e < ED) {
        row = ei[ED + e]; col = ei[e]; rt = et[e]; rt2 = -1;
    } else {
        const int* p = i2 + 4 * (e - ED);
        row = p[3]; col = p[0]; rt = p[1]; rt2 = p[2];
    }
    int p2 = atomicAdd(&((int*)(g_S + O_CUR))[row], 1);
    ((int4*)(g_S + O_SPK))[p2] = make_int4(col, rt, rt2, 0);
}

// ---------------- tf32 tensor-core GEMM, batched over shared A ----------------
__global__ __launch_bounds__(256) void k_gemm_tf32(const float* __restrict__ A,
                                                   const float* __restrict__ Bb,
                                                   float* __restrict__ Cb,
                                                   int M, int K,
                                                   int bStride, long long cStride) {
    __shared__ unsigned As[128][20];
    __shared__ unsigned Bs[16][136];
    const int tid = threadIdx.x;
    const int mat = blockIdx.x >> 1;
    const float* B = Bb + (size_t)mat * bStride;
    float* C = Cb + (size_t)mat * cStride;
    const int bm = blockIdx.y * 128, bn = (blockIdx.x & 1) * 128;
    const int w = tid >> 5, lane = tid & 31;
    const int wm = (w >> 1) * 32, wn = (w & 1) * 64;
    const int g = lane >> 2, t = lane & 3;

    float acc[2][8][4];
#pragma unroll
    for (int mi = 0; mi < 2; mi++)
#pragma unroll
        for (int ni = 0; ni < 8; ni++)
#pragma unroll
            for (int q = 0; q < 4; q++) acc[mi][ni][q] = 0.f;

    float4 ra[2], rb[2];
    auto ldA = [&](int k0) {
#pragma unroll
        for (int l = 0; l < 2; l++) {
            int idx = tid + 256 * l;
            int r = idx >> 2, c = (idx & 3) << 2;
            if (bm + r < M)
                ra[l] = *(const float4*)(A + (size_t)(bm + r) * K + k0 + c);
            else
                ra[l] = make_float4(0.f, 0.f, 0.f, 0.f);
        }
    };
    auto ldB = [&](int k0) {
#pragma unroll
        for (int l = 0; l < 2; l++) {
            int idx = tid + 256 * l;
            int r = idx >> 5, c = (idx & 31) << 2;
            rb[l] = *(const float4*)(B + (size_t)(k0 + r) * 256 + bn + c);
        }
    };
    ldA(0); ldB(0);

    for (int k0 = 0; k0 < K; k0 += 16) {
#pragma unroll
        for (int l = 0; l < 2; l++) {
            int idx = tid + 256 * l;
            int r = idx >> 2, c = (idx & 3) << 2;
            uint4 va = make_uint4(f2tf(ra[l].x), f2tf(ra[l].y), f2tf(ra[l].z), f2tf(ra[l].w));
            *(uint4*)&As[r][c] = va;
            int r2 = idx >> 5, c2 = (idx & 31) << 2;
            uint4 vb = make_uint4(f2tf(rb[l].x), f2tf(rb[l].y), f2tf(rb[l].z), f2tf(rb[l].w));
            *(uint4*)&Bs[r2][c2] = vb;
        }
        __syncthreads();
        if (k0 + 16 < K) { ldA(k0 + 16); ldB(k0 + 16); }
#pragma unroll
        for (int kk = 0; kk < 16; kk += 8) {
            unsigned af[2][4];
#pragma unroll
            for (int mi = 0; mi < 2; mi++) {
                int r0 = wm + mi * 16 + g;
                af[mi][0] = As[r0][kk + t];
                af[mi][1] = As[r0 + 8][kk + t];
                af[mi][2] = As[r0][kk + t + 4];
                af[mi][3] = As[r0 + 8][kk + t + 4];
            }
#pragma unroll
            for (int ni = 0; ni < 8; ni++) {
                int cn = wn + ni * 8 + g;
                unsigned b0 = Bs[kk + t][cn], b1 = Bs[kk + t + 4][cn];
#pragma unroll
                for (int mi = 0; mi < 2; mi++) {
                    asm volatile(
                        "mma.sync.aligned.m16n8k8.row.col.f32.tf32.tf32.f32 "
                        "{%0,%1,%2,%3},{%4,%5,%6,%7},{%8,%9},{%0,%1,%2,%3};\n"
                        : "+f"(acc[mi][ni][0]), "+f"(acc[mi][ni][1]),
                          "+f"(acc[mi][ni][2]), "+f"(acc[mi][ni][3])
                        : "r"(af[mi][0]), "r"(af[mi][1]), "r"(af[mi][2]), "r"(af[mi][3]),
                          "r"(b0), "r"(b1));
                }
            }
        }
        __syncthreads();
    }
#pragma unroll
    for (int mi = 0; mi < 2; mi++) {
        int r0 = bm + wm + mi * 16 + g;
#pragma unroll
        for (int ni = 0; ni < 8; ni++) {
            int cn = bn + wn + ni * 8 + 2 * t;
            if (r0 < M)
                *(float2*)(C + (size_t)r0 * 256 + cn) = make_float2(acc[mi][ni][0], acc[mi][ni][1]);
            if (r0 + 8 < M)
                *(float2*)(C + (size_t)(r0 + 8) * 256 + cn) = make_float2(acc[mi][ni][2], acc[mi][ni][3]);
        }
    }
}

// ---------------- layer 1: warp-per-node, single pass, ILP-2 ----------------
__global__ __launch_bounds__(256) void k_layer1(const float* __restrict__ ah) {
    int w = threadIdx.x >> 5, lane = threadIdx.x & 31;
    int n = blockIdx.x * 8 + w;
    if (n >= NE) return;
    const int* off = (const int*)(g_S + O_OFF);
    const int4* pk = (const int4*)(g_S + O_SPK);
    int s0 = off[n], s1 = off[n + 1];
    int li = lane * 4, ha = lane >> 4;
    const float* PAp = g_S + O_PA + (size_t)n * 256;
    float4 A0 = *(const float4*)(PAp + li);
    float4 A1 = *(const float4*)(PAp + 128 + li);
    float4 av0 = *(const float4*)(ah + ha * 64 + (li & 63));
    float4 av1 = *(const float4*)(ah + (2 + ha) * 64 + (li & 63));
    float sum0 = 0.f, sum1 = 0.f;
    float4 acc0 = make_float4(0, 0, 0, 0), acc1 = make_float4(0, 0, 0, 0);

    auto gath = [&](int4 r, float4& e0, float4& e1) {
        const float* PBp = g_S + O_PB + (size_t)r.x * 256;
        const float* PCp = g_S + O_PC + (size_t)r.y * 256;
        e0 = f4add(f4add(A0, *(const float4*)(PBp + li)), *(const float4*)(PCp + li));
        e1 = f4add(f4add(A1, *(const float4*)(PBp + 128 + li)), *(const float4*)(PCp + 128 + li));
        if (r.z >= 0) {
            const float* P2 = g_S + O_PC + (size_t)r.z * 256;
            e0 = f4add(e0, *(const float4*)(P2 + li));
            e1 = f4add(e1, *(const float4*)(P2 + 128 + li));
        }
    };
    auto accum = [&](float4 e0, float4 e1, float ex0, float ex1) {
        sum0 += ex0; sum1 += ex1;
        acc0.x += e0.x * ex0; acc0.y += e0.y * ex0; acc0.z += e0.z * ex0; acc0.w += e0.w * ex0;
        acc1.x += e1.x * ex1; acc1.y += e1.y * ex1; acc1.z += e1.z * ex1; acc1.w += e1.w * ex1;
    };

    int i = s0;
    for (; i + 1 < s1; i += 2) {
        int4 r1 = pk[i], r2 = pk[i + 1];
        float4 a0, a1, b0, b1;
        gath(r1, a0, a1);
        gath(r2, b0, b1);
        float dA0 = dot4(a0, av0), dA1 = dot4(a1, av1);
        float dB0 = dot4(b0, av0), dB1 = dot4(b1, av1);
#pragma unroll
        for (int o = 8; o >= 1; o >>= 1) {
            dA0 += __shfl_xor_sync(0xffffffffu, dA0, o);
            dA1 += __shfl_xor_sync(0xffffffffu, dA1, o);
            dB0 += __shfl_xor_sync(0xffffffffu, dB0, o);
            dB1 += __shfl_xor_sync(0xffffffffu, dB1, o);
        }
        float eA0 = __expf(lrelu(dA0)), eA1 = __expf(lrelu(dA1));
        float eB0 = __expf(lrelu(dB0)), eB1 = __expf(lrelu(dB1));
        accum(a0, a1, eA0, eA1);
        accum(b0, b1, eB0, eB1);
    }
    if (i < s1) {
        int4 r1 = pk[i];
        float4 a0, a1;
        gath(r1, a0, a1);
        float dA0 = dot4(a0, av0), dA1 = dot4(a1, av1);
#pragma unroll
        for (int o = 8; o >= 1; o >>= 1) {
            dA0 += __shfl_xor_sync(0xffffffffu, dA0, o);
            dA1 += __shfl_xor_sync(0xffffffffu, dA1, o);
        }
        accum(a0, a1, __expf(lrelu(dA0)), __expf(lrelu(dA1)));
    }
    float r0 = 1.f / (sum0 + 1e-16f), r1 = 1.f / (sum1 + 1e-16f);
    float* Xp = g_S + O_X + (size_t)n * 256;
    Xp[li + 0] = eluf(acc0.x * r0); Xp[li + 1] = eluf(acc0.y * r0);
    Xp[li + 2] = eluf(acc0.z * r0); Xp[li + 3] = eluf(acc0.w * r0);
    Xp[128 + li + 0] = eluf(acc1.x * r1); Xp[128 + li + 1] = eluf(acc1.y * r1);
    Xp[128 + li + 2] = eluf(acc1.z * r1); Xp[128 + li + 3] = eluf(acc1.w * r1);
}

// ---------------- layer 2: warp-per-node, single pass, ILP-2, + residual ----------------
__global__ __launch_bounds__(256) void k_layer2(const float* __restrict__ oa) {
    int w = threadIdx.x >> 5, lane = threadIdx.x & 31;
    int n = blockIdx.x * 8 + w;
    if (n >= NE) return;
    const int* off = (const int*)(g_S + O_OFF);
    const int4* pk = (const int4*)(g_S + O_SPK);
    int s0 = off[n], s1 = off[n + 1];
    int li = lane * 4;
    const float* QAp = g_S + O_QA + (size_t)n * 256;
    float4 A0 = *(const float4*)(QAp + li);
    float4 A1 = *(const float4*)(QAp + 128 + li);
    float4 ov0 = *(const float4*)(oa + li);
    float4 ov1 = *(const float4*)(oa + 128 + li);
    float sum = 0.f;
    float4 acc0 = make_float4(0, 0, 0, 0), acc1 = make_float4(0, 0, 0, 0);

    auto gath = [&](int4 r, float4& e0, float4& e1) {
        const float* QBp = g_S + O_QB + (size_t)r.x * 256;
        const float* QCp = g_S + O_QC + (size_t)r.y * 256;
        e0 = f4add(f4add(A0, *(const float4*)(QBp + li)), *(const float4*)(QCp + li));
        e1 = f4add(f4add(A1, *(const float4*)(QBp + 128 + li)), *(const float4*)(QCp + 128 + li));
        if (r.z >= 0) {
            const float* P2 = g_S + O_QC + (size_t)r.z * 256;
            e0 = f4add(e0, *(const float4*)(P2 + li));
            e1 = f4add(e1, *(const float4*)(P2 + 128 + li));
        }
    };
    auto accum = [&](float4 e0, float4 e1, float ex) {
        sum += ex;
        acc0.x += e0.x * ex; acc0.y += e0.y * ex; acc0.z += e0.z * ex; acc0.w += e0.w * ex;
        acc1.x += e1.x * ex; acc1.y += e1.y * ex; acc1.z += e1.z * ex; acc1.w += e1.w * ex;
    };

    int i = s0;
    for (; i + 1 < s1; i += 2) {
        int4 r1 = pk[i], r2 = pk[i + 1];
        float4 a0, a1, b0, b1;
        gath(r1, a0, a1);
        gath(r2, b0, b1);
        float dA = dot4(a0, ov0) + dot4(a1, ov1);
        float dB = dot4(b0, ov0) + dot4(b1, ov1);
#pragma unroll
        for (int o = 16; o >= 1; o >>= 1) {
            dA += __shfl_xor_sync(0xffffffffu, dA, o);
            dB += __shfl_xor_sync(0xffffffffu, dB, o);
        }
        accum(a0, a1, __expf(lrelu(dA)));
        accum(b0, b1, __expf(lrelu(dB)));
    }
    if (i < s1) {
        int4 r1 = pk[i];
        float4 a0, a1;
        gath(r1, a0, a1);
        float dA = dot4(a0, ov0) + dot4(a1, ov1);
#pragma unroll
        for (int o = 16; o >= 1; o >>= 1) dA += __shfl_xor_sync(0xffffffffu, dA, o);
        accum(a0, a1, __expf(lrelu(dA)));
    }
    float rs = 1.f / (sum + 1e-16f);
    const float* Ep = g_S + O_ENT + (size_t)n * 256;
    float* Xp = g_S + O_X + (size_t)n * 256;
    Xp[li + 0] = eluf(acc0.x * rs) + Ep[li + 0];
    Xp[li + 1] = eluf(acc0.y * rs) + Ep[li + 1];
    Xp[li + 2] = eluf(acc0.z * rs) + Ep[li + 2];
    Xp[li + 3] = eluf(acc0.w * rs) + Ep[li + 3];
    Xp[128 + li + 0] = eluf(acc1.x * rs) + Ep[128 + li + 0];
    Xp[128 + li + 1] = eluf(acc1.y * rs) + Ep[128 + li + 1];
    Xp[128 + li + 2] = eluf(acc1.z * rs) + Ep[128 + li + 2];
    Xp[128 + li + 3] = eluf(acc1.w * rs) + Ep[128 + li + 3];
}

// ---------------- BN ----------------
__global__ void k_fin1() {
    int c = threadIdx.x;
    float s = 0.f, q = 0.f;
    for (int r = blockIdx.x; r < NE; r += gridDim.x) {
        float y = g_S[O_X + (size_t)r * 256 + c];
        s += y; q += y * y;
    }
    atomicAdd(&g_S[O_CS + c], s);
    atomicAdd(&g_S[O_CQ + c], q);
}

__global__ void k_fin2() {
    int c = threadIdx.x;
    float mu = g_S[O_CS + c] / (float)NE;
    float var = g_S[O_CQ + c] / (float)NE - mu * mu;
    g_S[O_MU + c] = mu;
    g_S[O_RS + c] = rsqrtf(var + 1e-5f);
}

__global__ void k_fin3(float* __restrict__ out, const float* __restrict__ gam,
                       const float* __restrict__ bet) {
    size_t i = (size_t)blockIdx.x * blockDim.x + threadIdx.x;
    if (i >= SZ) return;
    int c = (int)(i & 255);
    float y = g_S[O_X + i];
    out[i] = (y - g_S[O_MU + c]) * g_S[O_RS + c] * gam[c] + bet[c];
}

// ---------------- launcher ----------------
extern "C" void kernel_launch(void* const* d_in, const int* in_sizes, int n_in,
                              void* d_out, int out_size) {
    const int*   ei  = (const int*)d_in[0];
    const int*   et  = (const int*)d_in[1];
    const int*   i2  = (const int*)d_in[2];
    const float* emb = (const float*)d_in[3];
    const float* rel = (const float*)d_in[4];
    const float* Wh  = (const float*)d_in[5];
    const float* ah  = (const float*)d_in[6];
    const float* gW  = (const float*)d_in[7];
    const float* oW  = (const float*)d_in[8];
    const float* oa  = (const float*)d_in[9];
    const float* We  = (const float*)d_in[10];
    const float* gam = (const float*)d_in[11];
    const float* bet = (const float*)d_in[12];
    float* out  = (float*)d_out;
    float* rout = out + SZ;  // r (500x256)

    float* S = nullptr;
    cudaGetSymbolAddress((void**)&S, g_S);

    // one-time side stream + events (created on first, non-captured, call)
    static bool tried = false, ok = false;
    static cudaStream_t sSide = 0;
    static cudaEvent_t evF = 0, evJ = 0;
    if (!tried) {
        tried = true;
        ok = (cudaStreamCreateWithFlags(&sSide, cudaStreamNonBlocking) == cudaSuccess) &&
             (cudaEventCreateWithFlags(&evF, cudaEventDisableTiming) == cudaSuccess) &&
             (cudaEventCreateWithFlags(&evJ, cudaEventDisableTiming) == cudaSuccess);
        if (!ok) sSide = 0;
    }
    cudaStream_t side = ok ? sSide : (cudaStream_t)0;

    const int eb = (ET + 255) / 256;
    dim3 gSmall(2, (NRL + 127) / 128);

    if (ok) { cudaEventRecord(evF, 0); cudaStreamWaitEvent(side, evF, 0); }

    // side chain: sort + rel-GEMMs (independent of main chain)
    k_zero<<<(NE + 255) / 256, 256, 0, side>>>();
    k_hist<<<eb, 256, 0, side>>>(ei, i2);
    k_scan1<<<SCAN_NB, 256, 0, side>>>();
    k_scan2<<<1, 256, 0, side>>>();
    k_scan3<<<SCAN_NB, 256, 0, side>>>();
    k_scatter<<<eb, 256, 0, side>>>(ei, et, i2);
    k_gemm_tf32<<<gSmall, 256, 0, side>>>(rel, gW, rout, NRL, 128, 0, 0);            // r
    k_gemm_tf32<<<gSmall, 256, 0, side>>>(rel, S + O_WC, S + O_PC, NRL, 128, 0, 0);  // PC

    // main chain: repack + fused GEMM-1 (PA,PB,ENT)
    k_prep_w<<<128, 256>>>(Wh, We);
    dim3 gBig1(6, (NE + 127) / 128);
    k_gemm_tf32<<<gBig1, 256>>>(emb, S + O_WA, S + O_PA, NE, 128,
                                128 * 256, (long long)SZ);

    if (ok) { cudaEventRecord(evJ, side); cudaStreamWaitEvent((cudaStream_t)0, evJ, 0); }

    k_layer1<<<(NE + 7) / 8, 256>>>(ah);

    dim3 gBig2(4, (NE + 127) / 128);
    k_gemm_tf32<<<gBig2, 256>>>(S + O_X, oW, S + O_QA, NE, 256,
                                256 * 256, (long long)SZ);
    k_gemm_tf32<<<gSmall, 256>>>(rout, oW + 512 * 256, S + O_QC, NRL, 256, 0, 0);    // QC

    k_layer2<<<(NE + 7) / 8, 256>>>(oa);

    k_fin1<<<512, 256>>>();
    k_fin2<<<1, 256>>>();
    k_fin3<<<(int)((SZ + 255) / 256), 256>>>(out, gam, bet);
}